// round 1
// baseline (speedup 1.0000x reference)
#include <cuda_runtime.h>
#include <cstdint>
#include <cstddef>

// SNN Leaky scan: mem_t = beta*mem_{t-1} + x_t - H(mem_{t-1}-1); spk_t = H(mem_t-1)
// Key identity: reset_{t+1} == spk_t, so one compare per step.
//
// Layout strategy: rows are independent chains -> 1 thread per row.
// Global traffic staged through SMEM with cp.async so all LDG/STG are fully
// coalesced (warp covers one contiguous 512B row-chunk). Tile is XOR-swizzled
// at float4 granularity so per-thread row reads (LDS.128) and writes (STS.128)
// are bank-conflict-free.

namespace {
constexpr int N_TOTAL = 8192;
constexpr int T_STEPS = 4000;
constexpr float BETA  = 0.95f;
constexpr float UTH   = 1.0f;

constexpr int ROWS    = 64;                 // rows per CTA (= threads)
constexpr int THREADS = 64;
constexpr int NWARPS  = THREADS / 32;       // 2
constexpr int TCHUNK  = 128;                // time steps per chunk (floats)
constexpr int TC4     = TCHUNK / 4;         // 32 float4 per row-chunk
constexpr int NCHUNK  = (T_STEPS + TCHUNK - 1) / TCHUNK;  // 32 (31 full + 32-step tail)
constexpr size_t SMEM_BYTES = 2ull * ROWS * TC4 * sizeof(float4);  // 64 KB, double buffered
}

__device__ __forceinline__ void cp_async16(void* sdst, const void* gsrc) {
    uint32_t s = (uint32_t)__cvta_generic_to_shared(sdst);
    asm volatile("cp.async.cg.shared.global [%0], [%1], 16;" :: "r"(s), "l"(gsrc));
}
__device__ __forceinline__ void cp_commit() {
    asm volatile("cp.async.commit_group;" ::: "memory");
}
template <int NN>
__device__ __forceinline__ void cp_wait() {
    asm volatile("cp.async.wait_group %0;" :: "n"(NN) : "memory");
}

// One SNN step. reset carried in-register; spike value IS next step's reset.
__device__ __forceinline__ void snn_step(float& mem, float& reset, float x, float& spk) {
    mem = __fmaf_rn(BETA, mem, x) - reset;   // 8-cyc serial chain (FFMA + FADD)
    spk = (mem > UTH) ? 1.0f : 0.0f;         // off critical path
    reset = spk;
}

__global__ void __launch_bounds__(THREADS, 1)
snn_leaky_kernel(const float* __restrict__ inp, float* __restrict__ out) {
    extern __shared__ float4 smem[];
    const int tid  = threadIdx.x;
    const int lane = tid & 31;
    const int wid  = tid >> 5;
    const int rowBase = blockIdx.x * ROWS;

    float4* buf0 = smem;
    float4* buf1 = smem + ROWS * TC4;

    // ---- preload chunk 0 (full chunk, no guard needed) ----
    for (int r = wid; r < ROWS; r += NWARPS) {
        const float4* g = reinterpret_cast<const float4*>(
            inp + (size_t)(rowBase + r) * T_STEPS);
        cp_async16(&buf0[r * TC4 + (lane ^ (r & 31))], g + lane);
    }
    cp_commit();

    float mem   = 0.0f;
    float reset = 0.0f;

    for (int c = 0; c < NCHUNK; ++c) {
        float4* cur = (c & 1) ? buf1 : buf0;
        float4* nxt = (c & 1) ? buf0 : buf1;
        const int tStart = c * TCHUNK;
        const int nv4    = min(TC4, (T_STEPS - tStart) >> 2);  // 32 or 8 (tail)

        // ---- issue async loads for chunk c+1, then ensure chunk c landed ----
        if (c + 1 < NCHUNK) {
            const int tS  = (c + 1) * TCHUNK;
            const int nvn = min(TC4, (T_STEPS - tS) >> 2);
            for (int r = wid; r < ROWS; r += NWARPS) {
                if (lane < nvn) {
                    const float4* g = reinterpret_cast<const float4*>(
                        inp + (size_t)(rowBase + r) * T_STEPS + tS);
                    cp_async16(&nxt[r * TC4 + (lane ^ (r & 31))], g + lane);
                }
            }
            cp_commit();
            cp_wait<1>();   // <=1 outstanding group => chunk c complete
        } else {
            cp_wait<0>();
        }
        __syncthreads();

        // ---- compute: thread 'tid' owns row 'tid'; spikes overwrite x in place ----
        {
            float4* rowp = cur + tid * TC4;
            const int sw = tid & 31;
            if (nv4 == TC4) {
                #pragma unroll
                for (int t4 = 0; t4 < TC4; ++t4) {
                    float4 x = rowp[t4 ^ sw];     // conflict-free LDS.128
                    float4 s;
                    snn_step(mem, reset, x.x, s.x);
                    snn_step(mem, reset, x.y, s.y);
                    snn_step(mem, reset, x.z, s.z);
                    snn_step(mem, reset, x.w, s.w);
                    rowp[t4 ^ sw] = s;            // conflict-free STS.128
                }
            } else {
                #pragma unroll 8
                for (int t4 = 0; t4 < nv4; ++t4) {
                    float4 x = rowp[t4 ^ sw];
                    float4 s;
                    snn_step(mem, reset, x.x, s.x);
                    snn_step(mem, reset, x.y, s.y);
                    snn_step(mem, reset, x.z, s.z);
                    snn_step(mem, reset, x.w, s.w);
                    rowp[t4 ^ sw] = s;
                }
            }
        }
        __syncthreads();

        // ---- coalesced store of spikes (warp per row-chunk) ----
        for (int r = wid; r < ROWS; r += NWARPS) {
            if (lane < nv4) {
                float4 v = cur[r * TC4 + (lane ^ (r & 31))];
                reinterpret_cast<float4*>(
                    out + (size_t)(rowBase + r) * T_STEPS + tStart)[lane] = v;
            }
        }
        __syncthreads();   // protects 'cur' before it is reloaded next iteration
    }
}

extern "C" void kernel_launch(void* const* d_in, const int* in_sizes, int n_in,
                              void* d_out, int out_size) {
    (void)in_sizes; (void)n_in; (void)out_size;
    const float* inp = (const float*)d_in[0];
    float* out = (float*)d_out;

    cudaFuncSetAttribute(snn_leaky_kernel,
                         cudaFuncAttributeMaxDynamicSharedMemorySize,
                         (int)SMEM_BYTES);
    snn_leaky_kernel<<<N_TOTAL / ROWS, THREADS, SMEM_BYTES>>>(inp, out);
}

// round 2
// speedup vs baseline: 1.0948x; 1.0948x over previous
#include <cuda_runtime.h>
#include <cstdint>
#include <cstddef>

// SNN Leaky scan, warp-specialized.
//   mem_t = beta*mem_{t-1} + x_t - reset_t ; reset_t = spk_{t-1} ; spk_t = H(mem_t - 1)
// Chain restructure (P = 8 cyc/step):
//   a     = fma(beta, mem, x)         (FFMA, 4)
//   mem   = a - freset                (FADD, 4)   <- mem chain = 8 cyc
//   p     = a > thr                   (FSETP, pred-as-data 4)   thr = 1 + freset in {1,2}
//   freset= p ? 1 : 0 ; thr = p ? 2 : 1   (SEL, 4) <- reset chain closes in 8 cyc, parallel
//   spk_t = freset'   (exact: mem_t>1  <=>  a_t > thr_t)
//
// Warps 0-1: compute (thread t owns row t).  Warps 2-3: all global I/O through a
// 3-buffer SMEM ring (cp.async 2 chunks ahead, coalesced float4 store of spikes),
// fully overlapped with compute. XOR-swizzled tiles: conflict-free LDS/STS both ways.

namespace {
constexpr int N_TOTAL  = 8192;
constexpr int T_STEPS  = 4000;
constexpr float BETA   = 0.95f;

constexpr int ROWS     = 64;     // rows per CTA
constexpr int CTHREADS = 64;     // compute threads (warps 0,1)
constexpr int THREADS  = 128;    // + io warps 2,3
constexpr int TCHUNK   = 128;    // time steps per chunk
constexpr int TC4      = TCHUNK / 4;                         // 32 float4 per row-chunk
constexpr int NCHUNK   = (T_STEPS + TCHUNK - 1) / TCHUNK;    // 32 (31 full + 32-step tail)
constexpr int NBUF     = 3;
constexpr size_t SMEM_BYTES = (size_t)NBUF * ROWS * TC4 * sizeof(float4);  // 96 KB
}

__device__ __forceinline__ void cp_async16(void* sdst, const void* gsrc) {
    uint32_t s = (uint32_t)__cvta_generic_to_shared(sdst);
    asm volatile("cp.async.cg.shared.global [%0], [%1], 16;" :: "r"(s), "l"(gsrc));
}
__device__ __forceinline__ void cp_commit() {
    asm volatile("cp.async.commit_group;" ::: "memory");
}
template <int NN>
__device__ __forceinline__ void cp_wait() {
    asm volatile("cp.async.wait_group %0;" :: "n"(NN) : "memory");
}

__device__ __forceinline__ void snn_step(float& mem, float& freset, float& thr,
                                         float x, float& spk) {
    float a = __fmaf_rn(BETA, mem, x);
    mem = a - freset;
    bool p = (a > thr);
    freset = p ? 1.0f : 0.0f;
    thr    = p ? 2.0f : 1.0f;
    spk = freset;
}

__global__ void __launch_bounds__(THREADS, 1)
snn_leaky_ws_kernel(const float* __restrict__ inp, float* __restrict__ out) {
    extern __shared__ float4 smem[];
    const int tid  = threadIdx.x;
    const int lane = tid & 31;
    const int rowBase = blockIdx.x * ROWS;
    const bool is_io = (tid >= CTHREADS);
    const int iow = (tid - CTHREADS) >> 5;   // 0 or 1 (io warps only)

    float4* buf[NBUF] = { smem, smem + ROWS * TC4, smem + 2 * ROWS * TC4 };

    // ---- prologue: io warps preload chunks 0 and 1 (each its own group) ----
    if (is_io) {
        for (int c0 = 0; c0 < 2; ++c0) {
            for (int r = iow; r < ROWS; r += 2) {
                const float4* g = reinterpret_cast<const float4*>(
                    inp + (size_t)(rowBase + r) * T_STEPS + c0 * TCHUNK);
                cp_async16(&buf[c0][r * TC4 + (lane ^ (r & 31))], g + lane);
            }
            cp_commit();
        }
    }

    float mem = 0.0f, freset = 0.0f, thr = 1.0f;

    for (int c = 0; c <= NCHUNK; ++c) {
        if (is_io) cp_wait<1>();   // chunk c load complete (<=1 group outstanding)
        __syncthreads();

        if (!is_io) {
            // ---- compute chunk c in place (spikes overwrite inputs) ----
            if (c < NCHUNK) {
                float4* rowp = buf[c % NBUF] + tid * TC4;
                const int sw = tid & 31;
                const int nv4 = min(TC4, (T_STEPS - c * TCHUNK) >> 2);  // 32 or 8
                if (nv4 == TC4) {
                    #pragma unroll
                    for (int t4 = 0; t4 < TC4; ++t4) {
                        float4 x = rowp[t4 ^ sw];
                        float4 s;
                        snn_step(mem, freset, thr, x.x, s.x);
                        snn_step(mem, freset, thr, x.y, s.y);
                        snn_step(mem, freset, thr, x.z, s.z);
                        snn_step(mem, freset, thr, x.w, s.w);
                        rowp[t4 ^ sw] = s;
                    }
                } else {
                    #pragma unroll
                    for (int t4 = 0; t4 < TC4 / 4; ++t4) {   // tail: 8 float4
                        float4 x = rowp[t4 ^ sw];
                        float4 s;
                        snn_step(mem, freset, thr, x.x, s.x);
                        snn_step(mem, freset, thr, x.y, s.y);
                        snn_step(mem, freset, thr, x.z, s.z);
                        snn_step(mem, freset, thr, x.w, s.w);
                        rowp[t4 ^ sw] = s;
                    }
                }
            }
        } else {
            // ---- store spikes of chunk c-1 (coalesced float4) ----
            if (c >= 1) {
                const int cp = c - 1;
                const int nv4 = min(TC4, (T_STEPS - cp * TCHUNK) >> 2);
                float4* b = buf[cp % NBUF];
                for (int r = iow; r < ROWS; r += 2) {
                    if (lane < nv4) {
                        float4 v = b[r * TC4 + (lane ^ (r & 31))];
                        reinterpret_cast<float4*>(
                            out + (size_t)(rowBase + r) * T_STEPS + cp * TCHUNK)[lane] = v;
                    }
                }
            }
            // ---- prefetch chunk c+2 ----
            if (c + 2 < NCHUNK) {
                const int cn = c + 2;
                const int nv4 = min(TC4, (T_STEPS - cn * TCHUNK) >> 2);
                float4* b = buf[cn % NBUF];
                for (int r = iow; r < ROWS; r += 2) {
                    if (lane < nv4) {
                        const float4* g = reinterpret_cast<const float4*>(
                            inp + (size_t)(rowBase + r) * T_STEPS + cn * TCHUNK);
                        cp_async16(&b[r * TC4 + (lane ^ (r & 31))], g + lane);
                    }
                }
            }
            cp_commit();   // unconditional: uniform per-thread group counting
        }
    }
}

extern "C" void kernel_launch(void* const* d_in, const int* in_sizes, int n_in,
                              void* d_out, int out_size) {
    (void)in_sizes; (void)n_in; (void)out_size;
    const float* inp = (const float*)d_in[0];
    float* out = (float*)d_out;

    cudaFuncSetAttribute(snn_leaky_ws_kernel,
                         cudaFuncAttributeMaxDynamicSharedMemorySize,
                         (int)SMEM_BYTES);
    snn_leaky_ws_kernel<<<N_TOTAL / ROWS, THREADS, SMEM_BYTES>>>(inp, out);
}